// round 1
// baseline (speedup 1.0000x reference)
#include <cuda_runtime.h>
#include <mma.h>

using namespace nvcuda;

// Problem constants
#define PB   64      // batch
#define PS   1024    // seq
#define PF   768     // features
#define PH   12      // heads
#define PDH  64      // head dim
#define PP2  64      // attended prefix length
#define NROW (PB * PP2)          // 4096 rows of the "active" matrix
#define HEADSZ 4096              // 64*64 per (b,h)

// Scratch: q/k/v [3][B][H][64][64] and attention output O [4096][768]
__device__ float g_qkv[3LL * PB * PH * PP2 * PDH];
__device__ float g_o[(long long)NROW * PF];

// ---------------------------------------------------------------------------
// Kernel 1: copy the pass-through tail x[:, 64:, :] -> out[:, 64:, :]
// ---------------------------------------------------------------------------
__global__ void copy_tail_kernel(const float4* __restrict__ x, float4* __restrict__ out) {
    const int ROW4 = PF / 4;                  // 192
    const int PERB = (PS - PP2) * ROW4;       // 184320 float4 per batch
    long long i = (long long)blockIdx.x * blockDim.x + threadIdx.x;
    if (i >= (long long)PB * PERB) return;
    int b   = (int)(i / PERB);
    int rem = (int)(i - (long long)b * PERB);
    long long off = (long long)b * PS * ROW4 + (long long)PP2 * ROW4 + rem;
    out[off] = x[off];
}

// ---------------------------------------------------------------------------
// TF32 WMMA GEMM, 128x64 block tile, BK=32, 256 threads (8 warps as 4x2).
// MODE 0: C[4096,2304] = Xw @ [Wq;Wk;Wv]^T + bias  -> g_qkv[which][b][h][s][d]
// MODE 1: C[4096, 768] = O  @ Wo^T          + bo   -> d_out[b][s][c] (s < 64)
// Each block's 64-column range lies inside exactly one (which, head).
// ---------------------------------------------------------------------------
#define GBM 128
#define GBN 64
#define GBK 32
#define GLDS 36   // BK + 4 pad
#define GLDC 68   // BN + 4 pad

template <int MODE>
__global__ void __launch_bounds__(256) gemm_kernel(
    const float* __restrict__ A,
    const float* __restrict__ W0, const float* __restrict__ W1, const float* __restrict__ W2,
    const float* __restrict__ b0, const float* __restrict__ b1, const float* __restrict__ b2,
    float* __restrict__ Cout)
{
    __shared__ __align__(16) float smem[GBM * GLDC];   // 34816 B, reused for C epilogue
    float* As = smem;                  // GBM*GLDS = 4608 floats
    float* Bs = smem + GBM * GLDS;     // GBN*GLDS = 2304 floats (total 6912 < 8704)
    float* Cs = smem;

    const int tid = threadIdx.x;
    const int wm  = (tid >> 5) >> 1;   // 0..3 (M)
    const int wn  = (tid >> 5) & 1;    // 0..1 (N)

    const float* Aptr = (MODE == 0) ? A : g_o;
    const float* W;
    const float* bias;
    int nbase;
    if (MODE == 0) {
        int wsel = blockIdx.y / 12;
        W    = (wsel == 0) ? W0 : (wsel == 1 ? W1 : W2);
        bias = (wsel == 0) ? b0 : (wsel == 1 ? b1 : b2);
        nbase = (blockIdx.y % 12) * 64;      // = h*64
    } else {
        W = W0; bias = b0; nbase = blockIdx.y * 64;
    }

    wmma::fragment<wmma::accumulator, 16, 16, 8, float> acc[2][2];
    #pragma unroll
    for (int i = 0; i < 2; i++)
        #pragma unroll
        for (int j = 0; j < 2; j++) wmma::fill_fragment(acc[i][j], 0.0f);

    const int m0 = blockIdx.x * GBM;
    const int lr = tid >> 3;             // 0..31
    const int lc = (tid & 7) * 4;        // 0..28

    for (int k0 = 0; k0 < PF; k0 += GBK) {
        // Load A tile 128x32 (float4, coalesced along K)
        #pragma unroll
        for (int p = 0; p < 4; p++) {
            int row = lr + p * 32;
            int r = m0 + row;
            const float* gp;
            if (MODE == 0) {
                gp = Aptr + ((long long)(r >> 6) * PS + (r & 63)) * PF + k0 + lc;
            } else {
                gp = Aptr + (long long)r * PF + k0 + lc;
            }
            float4 v = *reinterpret_cast<const float4*>(gp);
            float* d = As + row * GLDS + lc;
            d[0] = wmma::__float_to_tf32(v.x);
            d[1] = wmma::__float_to_tf32(v.y);
            d[2] = wmma::__float_to_tf32(v.z);
            d[3] = wmma::__float_to_tf32(v.w);
        }
        // Load B tile 64x32 (rows of W)
        #pragma unroll
        for (int p = 0; p < 2; p++) {
            int row = lr + p * 32;
            const float* gp = W + (long long)(nbase + row) * PF + k0 + lc;
            float4 v = *reinterpret_cast<const float4*>(gp);
            float* d = Bs + row * GLDS + lc;
            d[0] = wmma::__float_to_tf32(v.x);
            d[1] = wmma::__float_to_tf32(v.y);
            d[2] = wmma::__float_to_tf32(v.z);
            d[3] = wmma::__float_to_tf32(v.w);
        }
        __syncthreads();

        #pragma unroll
        for (int kk = 0; kk < GBK; kk += 8) {
            wmma::fragment<wmma::matrix_a, 16, 16, 8, wmma::precision::tf32, wmma::row_major> af[2];
            wmma::fragment<wmma::matrix_b, 16, 16, 8, wmma::precision::tf32, wmma::col_major> bf[2];
            wmma::load_matrix_sync(af[0], As + (wm * 32 +  0) * GLDS + kk, GLDS);
            wmma::load_matrix_sync(af[1], As + (wm * 32 + 16) * GLDS + kk, GLDS);
            wmma::load_matrix_sync(bf[0], Bs + (wn * 32 +  0) * GLDS + kk, GLDS);
            wmma::load_matrix_sync(bf[1], Bs + (wn * 32 + 16) * GLDS + kk, GLDS);
            #pragma unroll
            for (int i = 0; i < 2; i++)
                #pragma unroll
                for (int j = 0; j < 2; j++)
                    wmma::mma_sync(acc[i][j], af[i], bf[j], acc[i][j]);
        }
        __syncthreads();
    }

    // Epilogue: stage C in shared, add bias, scatter with layout mapping
    #pragma unroll
    for (int i = 0; i < 2; i++)
        #pragma unroll
        for (int j = 0; j < 2; j++)
            wmma::store_matrix_sync(Cs + (wm * 32 + i * 16) * GLDC + wn * 32 + j * 16,
                                    acc[i][j], GLDC, wmma::mem_row_major);
    __syncthreads();

    const int c4 = (tid & 15) * 4;
    const int r0 = tid >> 4;
    #pragma unroll
    for (int p = 0; p < 8; p++) {
        int row = r0 + p * 16;
        int r = m0 + row;
        float4 v = *reinterpret_cast<float4*>(Cs + row * GLDC + c4);
        v.x += bias[nbase + c4 + 0];
        v.y += bias[nbase + c4 + 1];
        v.z += bias[nbase + c4 + 2];
        v.w += bias[nbase + c4 + 3];
        if (MODE == 0) {
            int which = blockIdx.y / 12;
            int h = blockIdx.y % 12;
            long long addr = (long long)which * PB * PH * HEADSZ
                           + (long long)((r >> 6) * PH + h) * HEADSZ
                           + (long long)(r & 63) * 64 + c4;
            *reinterpret_cast<float4*>(&g_qkv[addr]) = v;
        } else {
            long long addr = ((long long)(r >> 6) * PS + (r & 63)) * PF + nbase + c4;
            *reinterpret_cast<float4*>(&Cout[addr]) = v;
        }
    }
}

// ---------------------------------------------------------------------------
// Kernel 3: attention core, one block per (b,h). 64x64 q,k,v tiles in smem.
// K tile XOR-swizzled so score-phase row reads are bank-conflict-free.
// ---------------------------------------------------------------------------
__global__ void __launch_bounds__(256) attn_kernel() {
    __shared__ float sq[64 * 64];   // q, later reused for v
    __shared__ float sk[64 * 64];   // k (swizzled)
    __shared__ float ss[64 * 64];   // scores -> attn weights

    const int b = blockIdx.x / PH;
    const int h = blockIdx.x % PH;
    const float* qg = g_qkv + (long long)(b * PH + h) * HEADSZ;
    const float* kg = qg + (long long)PB * PH * HEADSZ;
    const float* vg = kg + (long long)PB * PH * HEADSZ;

    const int tid  = threadIdx.x;
    const int lane = tid & 31;

    // Load q (linear) and k (swizzled: d ^ ((j&7)<<3))
    for (int t = tid; t < 1024; t += 256)
        reinterpret_cast<float4*>(sq)[t] = reinterpret_cast<const float4*>(qg)[t];
    for (int t = tid; t < 1024; t += 256) {
        int j = t >> 4, d4 = (t & 15) * 4;
        float4 v = reinterpret_cast<const float4*>(kg)[t];
        *reinterpret_cast<float4*>(&sk[j * 64 + (d4 ^ ((j & 7) << 3))]) = v;
    }
    __syncthreads();

    // scores[i][j] = dot(q_i, k_j) / 8
    #pragma unroll
    for (int t = 0; t < 16; t++) {
        int idx = tid + (t << 8);
        int i = idx >> 6, j = idx & 63;
        int sw = (j & 7) << 3;
        float s = 0.f;
        #pragma unroll
        for (int dd = 0; dd < 64; dd += 4) {
            float4 q4 = *reinterpret_cast<const float4*>(&sq[i * 64 + dd]);
            float4 k4 = *reinterpret_cast<const float4*>(&sk[j * 64 + (dd ^ sw)]);
            s += q4.x * k4.x + q4.y * k4.y + q4.z * k4.z + q4.w * k4.w;
        }
        ss[idx] = s * 0.125f;
    }
    __syncthreads();

    // row softmax: warp w handles rows [8w, 8w+8)
    {
        int w = tid >> 5;
        #pragma unroll
        for (int rr = 0; rr < 8; rr++) {
            int i = w * 8 + rr;
            float x0 = ss[i * 64 + lane];
            float x1 = ss[i * 64 + 32 + lane];
            float m = fmaxf(x0, x1);
            #pragma unroll
            for (int o = 16; o; o >>= 1) m = fmaxf(m, __shfl_xor_sync(0xffffffffu, m, o));
            float e0 = __expf(x0 - m), e1 = __expf(x1 - m);
            float sum = e0 + e1;
            #pragma unroll
            for (int o = 16; o; o >>= 1) sum += __shfl_xor_sync(0xffffffffu, sum, o);
            float inv = 1.0f / sum;
            ss[i * 64 + lane]      = e0 * inv;
            ss[i * 64 + 32 + lane] = e1 * inv;
        }
    }
    __syncthreads();

    // reload v over q
    for (int t = tid; t < 1024; t += 256)
        reinterpret_cast<float4*>(sq)[t] = reinterpret_cast<const float4*>(vg)[t];
    __syncthreads();

    // o[i][d] = sum_j attn[i][j] * v[j][d]; write as O[b*64+i][h*64+d]
    #pragma unroll
    for (int t = 0; t < 4; t++) {
        int g = tid + (t << 8);
        int i  = g >> 4;
        int d4 = (g & 15) * 4;
        float ox = 0.f, oy = 0.f, oz = 0.f, ow = 0.f;
        #pragma unroll 16
        for (int j = 0; j < 64; j++) {
            float a = ss[i * 64 + j];
            float4 v4 = *reinterpret_cast<const float4*>(&sq[j * 64 + d4]);
            ox += a * v4.x; oy += a * v4.y; oz += a * v4.z; ow += a * v4.w;
        }
        float4 o4; o4.x = ox; o4.y = oy; o4.z = oz; o4.w = ow;
        *reinterpret_cast<float4*>(&g_o[(long long)(b * 64 + i) * PF + h * 64 + d4]) = o4;
    }
}

// ---------------------------------------------------------------------------
extern "C" void kernel_launch(void* const* d_in, const int* in_sizes, int n_in,
                              void* d_out, int out_size) {
    const float* x  = (const float*)d_in[0];
    const float* Wq = (const float*)d_in[1];
    const float* bq = (const float*)d_in[2];
    const float* Wk = (const float*)d_in[3];
    const float* bk = (const float*)d_in[4];
    const float* Wv = (const float*)d_in[5];
    const float* bv = (const float*)d_in[6];
    const float* Wo = (const float*)d_in[7];
    const float* bo = (const float*)d_in[8];
    float* out = (float*)d_out;

    // 1) pass-through tail (memory-bound, launched first)
    long long tail4 = (long long)PB * (PS - PP2) * (PF / 4);
    copy_tail_kernel<<<(unsigned)((tail4 + 255) / 256), 256>>>(
        (const float4*)x, (float4*)out);

    // 2) fused QKV projection (+bias) into scratch
    gemm_kernel<0><<<dim3(32, 36), 256>>>(x, Wq, Wk, Wv, bq, bk, bv, nullptr);

    // 3) attention per (b,h)
    attn_kernel<<<PB * PH, 256>>>();

    // 4) output projection (+bo) straight into d_out[:, :64, :]
    gemm_kernel<1><<<dim3(32, 12), 256>>>(nullptr, Wo, nullptr, nullptr,
                                          bo, nullptr, nullptr, out);
}